// round 1
// baseline (speedup 1.0000x reference)
#include <cuda_runtime.h>
#include <cuda_bf16.h>
#include <math.h>
#include <stdint.h>
#include <stddef.h>

// Problem constants
#define NTOK   2048
#define DMODEL 2048
#define NHEADS 16
#define HDIM   128     // DMODEL / NHEADS
#define NROUNDS 2

// ---------------------------------------------------------------------------
// Scratch (no cudaMalloc allowed -> __device__ globals)
// ---------------------------------------------------------------------------
__device__ float g_E[(size_t)NTOK * DMODEL];   // entities after round 0
__device__ float g_Q[(size_t)NTOK * DMODEL];
__device__ float g_K[(size_t)NTOK * DMODEL];
__device__ float g_V[(size_t)NTOK * DMODEL];
__device__ float g_O[(size_t)NTOK * DMODEL];   // merged attention output
__device__ float g_T[(size_t)NTOK * DMODEL];   // ffn0 output
__device__ float g_S[(size_t)NHEADS * NTOK * NTOK]; // scores / probs (256 MB)

// ---------------------------------------------------------------------------
// Tiled fp32 GEMM: C = alpha * A * op(B) + bias (+relu) (+resid)
//   BTRANS=true : op(B) = B^T where B is [N, K] row-major   (y = x @ W^T)
//   BTRANS=false: op(B) = B   where B is [K, N] row-major   (o = P @ V)
// A is [M, K] row-major. 128x128 block tile, K-step 8, 256 threads, 8x8/thread.
// blockIdx.z applies per-head element strides (aHS/bHS/cHS).
// M, N multiples of 128 and K multiple of 8 are assumed (true for all calls).
// ---------------------------------------------------------------------------
template <bool BTRANS>
__global__ void __launch_bounds__(256)
gemm_kernel(const float* __restrict__ A, int lda, size_t aHS,
            const float* __restrict__ B, int ldb, size_t bHS,
            const float* __restrict__ bias,
            const float* __restrict__ resid, int ldr,
            float* __restrict__ C, int ldc, size_t cHS,
            int K, float alpha, int doRelu)
{
    __shared__ __align__(16) float As[2][8][132];
    __shared__ __align__(16) float Bs[2][8][132];

    const int z = blockIdx.z;
    A += (size_t)z * aHS;
    B += (size_t)z * bHS;
    C += (size_t)z * cHS;

    const int tid = threadIdx.x;
    const int m0  = blockIdx.y * 128;
    const int n0  = blockIdx.x * 128;

    // A tile load: 128 rows x 8 k-cols = 256 float4 (one per thread)
    const int arow = tid >> 1;            // 0..127
    const int acol = (tid & 1) << 2;      // 0 or 4
    const float* aPtr = A + (size_t)(m0 + arow) * lda + acol;

    // B tile load
    int brow, bcol;
    const float* bPtr;
    if (BTRANS) {
        brow = tid >> 1;                  // n index 0..127
        bcol = (tid & 1) << 2;            // k offset 0 or 4
        bPtr = B + (size_t)(n0 + brow) * ldb + bcol;
    } else {
        brow = tid >> 5;                  // k index 0..7
        bcol = (tid & 31) << 2;           // n offset 0..124
        bPtr = B + (size_t)brow * ldb + (n0 + bcol);
    }

    float4 aReg = *reinterpret_cast<const float4*>(aPtr);
    float4 bReg = *reinterpret_cast<const float4*>(bPtr);

    float acc[8][8];
#pragma unroll
    for (int i = 0; i < 8; i++)
#pragma unroll
        for (int j = 0; j < 8; j++) acc[i][j] = 0.f;

    const int ry = (tid >> 4) << 3;  // row offset within tile (0..120)
    const int rx = (tid & 15) << 3;  // col offset within tile (0..120)

    const int ntiles = K >> 3;
    int buf = 0;

    // stage first tile into smem
    As[0][acol + 0][arow] = aReg.x;
    As[0][acol + 1][arow] = aReg.y;
    As[0][acol + 2][arow] = aReg.z;
    As[0][acol + 3][arow] = aReg.w;
    if (BTRANS) {
        Bs[0][bcol + 0][brow] = bReg.x;
        Bs[0][bcol + 1][brow] = bReg.y;
        Bs[0][bcol + 2][brow] = bReg.z;
        Bs[0][bcol + 3][brow] = bReg.w;
    } else {
        *reinterpret_cast<float4*>(&Bs[0][brow][bcol]) = bReg;
    }

    for (int t = 0; t < ntiles; t++) {
        __syncthreads();
        const bool more = (t + 1 < ntiles);
        if (more) {
            aReg = *reinterpret_cast<const float4*>(aPtr + (size_t)(t + 1) * 8);
            if (BTRANS)
                bReg = *reinterpret_cast<const float4*>(bPtr + (size_t)(t + 1) * 8);
            else
                bReg = *reinterpret_cast<const float4*>(bPtr + (size_t)(t + 1) * 8 * ldb);
        }

#pragma unroll
        for (int k = 0; k < 8; k++) {
            float4 a0 = *reinterpret_cast<const float4*>(&As[buf][k][ry]);
            float4 a1 = *reinterpret_cast<const float4*>(&As[buf][k][ry + 4]);
            float4 b0 = *reinterpret_cast<const float4*>(&Bs[buf][k][rx]);
            float4 b1 = *reinterpret_cast<const float4*>(&Bs[buf][k][rx + 4]);
            float av[8] = {a0.x, a0.y, a0.z, a0.w, a1.x, a1.y, a1.z, a1.w};
            float bv[8] = {b0.x, b0.y, b0.z, b0.w, b1.x, b1.y, b1.z, b1.w};
#pragma unroll
            for (int i = 0; i < 8; i++)
#pragma unroll
                for (int j = 0; j < 8; j++)
                    acc[i][j] = fmaf(av[i], bv[j], acc[i][j]);
        }

        if (more) {
            buf ^= 1;
            As[buf][acol + 0][arow] = aReg.x;
            As[buf][acol + 1][arow] = aReg.y;
            As[buf][acol + 2][arow] = aReg.z;
            As[buf][acol + 3][arow] = aReg.w;
            if (BTRANS) {
                Bs[buf][bcol + 0][brow] = bReg.x;
                Bs[buf][bcol + 1][brow] = bReg.y;
                Bs[buf][bcol + 2][brow] = bReg.z;
                Bs[buf][bcol + 3][brow] = bReg.w;
            } else {
                *reinterpret_cast<float4*>(&Bs[buf][brow][bcol]) = bReg;
            }
        }
    }

    // Epilogue: alpha, +bias, relu, +resid (matching reference order:
    // o = relu(x@W^T + b); out = resid + o)
#pragma unroll
    for (int i = 0; i < 8; i++) {
        const int row = m0 + ry + i;
        float* cRow = C + (size_t)row * ldc + (n0 + rx);
        const float* rRow = resid ? (resid + (size_t)row * ldr + (n0 + rx)) : nullptr;
#pragma unroll
        for (int j = 0; j < 8; j++) {
            float v = acc[i][j] * alpha;
            if (bias)  v += bias[n0 + rx + j];
            if (doRelu) v = fmaxf(v, 0.f);
            if (rRow)  v += rRow[j];
            cRow[j] = v;
        }
    }
}

// ---------------------------------------------------------------------------
// Row softmax over 2048 columns. One block (256 threads) per row.
// ---------------------------------------------------------------------------
__global__ void __launch_bounds__(256)
softmax_kernel(float* __restrict__ S)
{
    float* row = S + (size_t)blockIdx.x * NTOK;
    const int tid  = threadIdx.x;
    const int lane = tid & 31;
    const int wid  = tid >> 5;

    float v[8];
    float m = -INFINITY;
#pragma unroll
    for (int i = 0; i < 8; i++) {
        v[i] = row[tid + i * 256];
        m = fmaxf(m, v[i]);
    }
#pragma unroll
    for (int off = 16; off > 0; off >>= 1)
        m = fmaxf(m, __shfl_xor_sync(0xFFFFFFFFu, m, off));

    __shared__ float redMax[8];
    __shared__ float redSum[8];
    if (lane == 0) redMax[wid] = m;
    __syncthreads();
    float bm = -INFINITY;
#pragma unroll
    for (int w = 0; w < 8; w++) bm = fmaxf(bm, redMax[w]);

    float s = 0.f;
#pragma unroll
    for (int i = 0; i < 8; i++) {
        v[i] = __expf(v[i] - bm);
        s += v[i];
    }
#pragma unroll
    for (int off = 16; off > 0; off >>= 1)
        s += __shfl_xor_sync(0xFFFFFFFFu, s, off);
    if (lane == 0) redSum[wid] = s;
    __syncthreads();
    float tot = 0.f;
#pragma unroll
    for (int w = 0; w < 8; w++) tot += redSum[w];

    const float inv = 1.f / tot;
#pragma unroll
    for (int i = 0; i < 8; i++)
        row[tid + i * 256] = v[i] * inv;
}

// ---------------------------------------------------------------------------
// Host driver. All launches on the default stream, graph-capturable.
// Input order (metadata): entities, Wq, bq, Wk, bk, Wv, bv, W0, b0, W1, b1
// ---------------------------------------------------------------------------
extern "C" void kernel_launch(void* const* d_in, const int* in_sizes, int n_in,
                              void* d_out, int out_size)
{
    const float* ent = (const float*)d_in[0];
    const float* Wq  = (const float*)d_in[1];
    const float* bq  = (const float*)d_in[2];
    const float* Wk  = (const float*)d_in[3];
    const float* bk  = (const float*)d_in[4];
    const float* Wv  = (const float*)d_in[5];
    const float* bv  = (const float*)d_in[6];
    const float* W0  = (const float*)d_in[7];
    const float* b0  = (const float*)d_in[8];
    const float* W1  = (const float*)d_in[9];
    const float* b1  = (const float*)d_in[10];
    float* out = (float*)d_out;

    float *Eb, *Qb, *Kb, *Vb, *Ob, *Tb, *Sb;
    cudaGetSymbolAddress((void**)&Eb, g_E);
    cudaGetSymbolAddress((void**)&Qb, g_Q);
    cudaGetSymbolAddress((void**)&Kb, g_K);
    cudaGetSymbolAddress((void**)&Vb, g_V);
    cudaGetSymbolAddress((void**)&Ob, g_O);
    cudaGetSymbolAddress((void**)&Tb, g_T);
    cudaGetSymbolAddress((void**)&Sb, g_S);

    const dim3 thr(256);
    const dim3 gFull(16, 16, 1);         // 2048x2048 output
    const dim3 gScores(16, 16, NHEADS);  // per-head 2048x2048 scores
    const dim3 gPV(1, 16, NHEADS);       // per-head 2048x128 output
    const float scale = 0.08838834764831845f;  // 1/sqrt(128)
    const size_t headS = (size_t)NTOK * NTOK;

    for (int r = 0; r < NROUNDS; r++) {
        const float* src = (r == 0) ? ent : Eb;
        float*       dst = (r == 0) ? Eb  : out;

        // Q, K, V projections: y = src @ W^T + b
        gemm_kernel<true><<<gFull, thr>>>(src, DMODEL, 0, Wq, DMODEL, 0, bq,
                                          nullptr, 0, Qb, DMODEL, 0,
                                          DMODEL, 1.f, 0);
        gemm_kernel<true><<<gFull, thr>>>(src, DMODEL, 0, Wk, DMODEL, 0, bk,
                                          nullptr, 0, Kb, DMODEL, 0,
                                          DMODEL, 1.f, 0);
        gemm_kernel<true><<<gFull, thr>>>(src, DMODEL, 0, Wv, DMODEL, 0, bv,
                                          nullptr, 0, Vb, DMODEL, 0,
                                          DMODEL, 1.f, 0);

        // scores[h] = scale * Q_h @ K_h^T   (K-dim = 128 per head)
        gemm_kernel<true><<<gScores, thr>>>(Qb, DMODEL, HDIM, Kb, DMODEL, HDIM,
                                            nullptr, nullptr, 0,
                                            Sb, NTOK, headS,
                                            HDIM, scale, 0);

        // softmax over last dim
        softmax_kernel<<<NHEADS * NTOK, thr>>>(Sb);

        // O_h = P_h @ V_h   (NN gemm, K-dim = 2048)
        gemm_kernel<false><<<gPV, thr>>>(Sb, NTOK, headS, Vb, DMODEL, HDIM,
                                         nullptr, nullptr, 0,
                                         Ob, DMODEL, HDIM,
                                         NTOK, 1.f, 0);

        // T = relu(O @ W0^T + b0)
        gemm_kernel<true><<<gFull, thr>>>(Ob, DMODEL, 0, W0, DMODEL, 0, b0,
                                          nullptr, 0, Tb, DMODEL, 0,
                                          DMODEL, 1.f, 1);

        // dst = src + relu(T @ W1^T + b1)
        gemm_kernel<true><<<gFull, thr>>>(Tb, DMODEL, 0, W1, DMODEL, 0, b1,
                                          src, DMODEL, dst, DMODEL, 0,
                                          DMODEL, 1.f, 1);
    }
}

// round 3
// speedup vs baseline: 2.7657x; 2.7657x over previous
#include <cuda_runtime.h>
#include <cuda_bf16.h>
#include <stdint.h>
#include <stddef.h>
#include <math.h>

#define NTOK   2048
#define DMODEL 2048
#define NHEADS 16
#define HDIM   128
#define NELEM  ((size_t)NTOK * DMODEL)
#define SHEAD  ((size_t)NTOK * NTOK)
#define NSC    ((size_t)NHEADS * NTOK * NTOK)

// ---------------------------------------------------------------------------
// Scratch (__device__ globals; no cudaMalloc allowed)
// ---------------------------------------------------------------------------
__device__ __align__(16) float         g_E32[NELEM];
__device__ __align__(16) __nv_bfloat16 g_Ehi[NELEM],  g_Elo[NELEM];
__device__ __align__(16) __nv_bfloat16 g_Qhi[NELEM],  g_Qlo[NELEM];
__device__ __align__(16) __nv_bfloat16 g_Khi[NELEM],  g_Klo[NELEM];
__device__ __align__(16) __nv_bfloat16 g_Vthi[NELEM], g_Vtlo[NELEM];
__device__ __align__(16) __nv_bfloat16 g_Ohi[NELEM],  g_Olo[NELEM];
__device__ __align__(16) __nv_bfloat16 g_Thi[NELEM],  g_Tlo[NELEM];
__device__ __align__(16) __nv_bfloat16 g_Wqhi[NELEM], g_Wqlo[NELEM];
__device__ __align__(16) __nv_bfloat16 g_Wkhi[NELEM], g_Wklo[NELEM];
__device__ __align__(16) __nv_bfloat16 g_Wvhi[NELEM], g_Wvlo[NELEM];
__device__ __align__(16) __nv_bfloat16 g_W0hi[NELEM], g_W0lo[NELEM];
__device__ __align__(16) __nv_bfloat16 g_W1hi[NELEM], g_W1lo[NELEM];
__device__ __align__(16) float         g_S[NSC];
__device__ __align__(16) __nv_bfloat16 g_Phi[NSC],    g_Plo[NSC];

// ---------------------------------------------------------------------------
// PTX helpers (sm_80-era: cp.async, ldmatrix, mma.sync — valid on sm_100 base)
// ---------------------------------------------------------------------------
__device__ __forceinline__ uint32_t smem_u32(const void* p) {
    uint32_t a;
    asm("{ .reg .u64 t; cvta.to.shared.u64 t, %1; cvt.u32.u64 %0, t; }" : "=r"(a) : "l"(p));
    return a;
}
__device__ __forceinline__ void cpasync16(uint32_t dst, const void* src) {
    asm volatile("cp.async.cg.shared.global [%0], [%1], 16;" :: "r"(dst), "l"(src));
}
__device__ __forceinline__ void cp_commit() {
    asm volatile("cp.async.commit_group;" ::: "memory");
}
__device__ __forceinline__ void cp_wait1() {
    asm volatile("cp.async.wait_group 1;" ::: "memory");
}
__device__ __forceinline__ void ldsm4(uint32_t* d, uint32_t addr) {
    asm volatile("ldmatrix.sync.aligned.m8n8.x4.shared.b16 {%0,%1,%2,%3}, [%4];"
                 : "=r"(d[0]), "=r"(d[1]), "=r"(d[2]), "=r"(d[3]) : "r"(addr));
}
__device__ __forceinline__ void ldsm2(uint32_t* d, uint32_t addr) {
    asm volatile("ldmatrix.sync.aligned.m8n8.x2.shared.b16 {%0,%1}, [%2];"
                 : "=r"(d[0]), "=r"(d[1]) : "r"(addr));
}
__device__ __forceinline__ void mma_bf16(float* c, const uint32_t* a, const uint32_t* b) {
    asm volatile(
        "mma.sync.aligned.m16n8k16.row.col.f32.bf16.bf16.f32 "
        "{%0,%1,%2,%3}, {%4,%5,%6,%7}, {%8,%9}, {%0,%1,%2,%3};"
        : "+f"(c[0]), "+f"(c[1]), "+f"(c[2]), "+f"(c[3])
        : "r"(a[0]), "r"(a[1]), "r"(a[2]), "r"(a[3]), "r"(b[0]), "r"(b[1]));
}

// ---------------------------------------------------------------------------
// bf16x3 GEMM: D[m,n] = alpha * sum_k A[m,k]*B[n,k] (+bias)(+relu)(+resid)
//   A = Ahi+Alo, B = Bhi+Blo (bf16 pairs); acc += AhiBhi + AloBhi + AhiBlo.
// Tile: BM=256, BN=128, BK=64. 512 threads (16 warps, 64x32 each).
// All matrices row-major with stride 2048 elements. blockIdx.z = head,
// aHS/bHS/... are per-head element offsets.
// biasMode: 0 none, 1 bias[col], 2 bias[row].
// ---------------------------------------------------------------------------
#define SMSTRIDE 144                    // bytes per 64-elem bf16 row (128+16)
#define A_LO_OFF  36864                 // 256*144
#define B_HI_OFF  73728
#define B_LO_OFF  92160                 // +128*144
#define STAGE_SZ 110592                 // 768*144
#define SMEM_TOT (2 * STAGE_SZ)        // 221184

__global__ void __launch_bounds__(512, 1)
gemm_mma(const __nv_bfloat16* __restrict__ Ahi, const __nv_bfloat16* __restrict__ Alo,
         unsigned long long aHS,
         const __nv_bfloat16* __restrict__ Bhi, const __nv_bfloat16* __restrict__ Blo,
         unsigned long long bHS,
         const float* __restrict__ bias, int biasMode, int doRelu,
         const float* __restrict__ resid, unsigned long long rHS,
         float* __restrict__ outF, unsigned long long oHS,
         __nv_bfloat16* __restrict__ outHi, __nv_bfloat16* __restrict__ outLo,
         unsigned long long hHS,
         int K, float alpha)
{
    extern __shared__ __align__(128) char dsm[];
    const uint32_t smBase = smem_u32(dsm);

    const int tid  = threadIdx.x;
    const int lane = tid & 31;
    const int w    = tid >> 5;           // 0..15
    const int warpM = w & 3;             // 4 x 64 rows
    const int warpN = w >> 2;            // 4 x 32 cols
    const int z  = blockIdx.z;
    const int m0 = blockIdx.y * 256;
    const int n0 = blockIdx.x * 128;

    const __nv_bfloat16* Ah = Ahi + (size_t)z * aHS;
    const __nv_bfloat16* Al = Alo + (size_t)z * aHS;
    const __nv_bfloat16* Bh = Bhi + (size_t)z * bHS;
    const __nv_bfloat16* Bl = Blo + (size_t)z * bHS;

    const int ntiles = K >> 6;

    // ---- stage loader: 12 cp.async per thread ----
    auto load_stage = [&](int s, int t) {
        const uint32_t base = smBase + s * STAGE_SZ;
        const int k0 = t << 6;
#pragma unroll
        for (int j = 0; j < 4; j++) {                 // A tiles: 2048 chunks
            int i = tid + j * 512;
            int r = i >> 3, c = i & 7;
            uint32_t off = r * SMSTRIDE + c * 16;
            const size_t g = (size_t)(m0 + r) * DMODEL + k0 + c * 8;
            cpasync16(base + off,            Ah + g);
            cpasync16(base + A_LO_OFF + off, Al + g);
        }
#pragma unroll
        for (int j = 0; j < 2; j++) {                 // B tiles: 1024 chunks
            int i = tid + j * 512;
            int r = i >> 3, c = i & 7;
            uint32_t off = r * SMSTRIDE + c * 16;
            const size_t g = (size_t)(n0 + r) * DMODEL + k0 + c * 8;
            cpasync16(base + B_HI_OFF + off, Bh + g);
            cpasync16(base + B_LO_OFF + off, Bl + g);
        }
    };

    float c[4][4][4];
#pragma unroll
    for (int i = 0; i < 4; i++)
#pragma unroll
        for (int j = 0; j < 4; j++)
#pragma unroll
            for (int p = 0; p < 4; p++) c[i][j][p] = 0.f;

    // per-warp ldmatrix base offsets (within a stage)
    const uint32_t aOff = (uint32_t)(warpM * 64 + (lane & 15)) * SMSTRIDE
                        + ((lane >> 4) & 1) * 16;
    const uint32_t bOff = B_HI_OFF
                        + (uint32_t)(warpN * 32 + (lane & 7)) * SMSTRIDE
                        + ((lane >> 3) & 1) * 16;

    // ---- prologue ----
    load_stage(0, 0); cp_commit();
    load_stage(1, 1); cp_commit();
    cp_wait1();
    __syncthreads();

    for (int t = 0; t < ntiles; t++) {
        const int buf = t & 1;
        const uint32_t stA = smBase + buf * STAGE_SZ + aOff;
        const uint32_t stB = smBase + buf * STAGE_SZ + bOff;

#pragma unroll
        for (int ks = 0; ks < 4; ks++) {
            const uint32_t ko = ks * 32;   // 16 bf16 = 32 bytes
            uint32_t aH[4][4], aL[4][4], bH[4][2], bL[4][2];
#pragma unroll
            for (int mt = 0; mt < 4; mt++) ldsm4(aH[mt], stA + mt * (16 * SMSTRIDE) + ko);
#pragma unroll
            for (int nt = 0; nt < 4; nt++) ldsm2(bH[nt], stB + nt * (8 * SMSTRIDE) + ko);
#pragma unroll
            for (int mt = 0; mt < 4; mt++)
#pragma unroll
                for (int nt = 0; nt < 4; nt++) mma_bf16(c[mt][nt], aH[mt], bH[nt]);
#pragma unroll
            for (int mt = 0; mt < 4; mt++)
                ldsm4(aL[mt], stA + A_LO_OFF + mt * (16 * SMSTRIDE) + ko);
#pragma unroll
            for (int mt = 0; mt < 4; mt++)
#pragma unroll
                for (int nt = 0; nt < 4; nt++) mma_bf16(c[mt][nt], aL[mt], bH[nt]);
#pragma unroll
            for (int nt = 0; nt < 4; nt++)
                ldsm2(bL[nt], stB + (B_LO_OFF - B_HI_OFF) + nt * (8 * SMSTRIDE) + ko);
#pragma unroll
            for (int mt = 0; mt < 4; mt++)
#pragma unroll
                for (int nt = 0; nt < 4; nt++) mma_bf16(c[mt][nt], aH[mt], bL[nt]);
        }

        __syncthreads();                 // everyone done reading buf
        if (t + 2 < ntiles) load_stage(buf, t + 2);
        cp_commit();                     // possibly empty group
        cp_wait1();                      // next stage resident
        __syncthreads();
    }

    // ---- epilogue: fused alpha/bias/relu/resid + fp32 and/or bf16 hi/lo ----
    const int g  = lane >> 2;
    const int tg = lane & 3;
    const float* residZ = resid ? resid + (size_t)z * rHS : nullptr;
    float* outFZ = outF ? outF + (size_t)z * oHS : nullptr;
    __nv_bfloat16* outHiZ = outHi ? outHi + (size_t)z * hHS : nullptr;
    __nv_bfloat16* outLoZ = outLo ? outLo + (size_t)z * hHS : nullptr;

#pragma unroll
    for (int mt = 0; mt < 4; mt++) {
#pragma unroll
        for (int nt = 0; nt < 4; nt++) {
            const int col = n0 + warpN * 32 + nt * 8 + tg * 2;
#pragma unroll
            for (int p = 0; p < 2; p++) {
                const int row = m0 + warpM * 64 + mt * 16 + g + p * 8;
                float v0 = c[mt][nt][2 * p]     * alpha;
                float v1 = c[mt][nt][2 * p + 1] * alpha;
                if (biasMode == 1) { v0 += bias[col]; v1 += bias[col + 1]; }
                else if (biasMode == 2) { const float rb = bias[row]; v0 += rb; v1 += rb; }
                if (doRelu) { v0 = fmaxf(v0, 0.f); v1 = fmaxf(v1, 0.f); }
                if (residZ) {
                    const float2 rv = *(const float2*)(residZ + (size_t)row * DMODEL + col);
                    v0 += rv.x; v1 += rv.y;
                }
                if (outFZ) {
                    float2 ov = {v0, v1};
                    *(float2*)(outFZ + (size_t)row * DMODEL + col) = ov;
                }
                if (outHiZ) {
                    __nv_bfloat16 h0 = __float2bfloat16(v0);
                    __nv_bfloat16 h1 = __float2bfloat16(v1);
                    *(__nv_bfloat162*)(outHiZ + (size_t)row * DMODEL + col) =
                        __nv_bfloat162{h0, h1};
                    *(__nv_bfloat162*)(outLoZ + (size_t)row * DMODEL + col) =
                        __nv_bfloat162{__float2bfloat16(v0 - __bfloat162float(h0)),
                                       __float2bfloat16(v1 - __bfloat162float(h1))};
                }
            }
        }
    }
}

// ---------------------------------------------------------------------------
// fp32 -> (bf16 hi, bf16 lo) split, x4 vectorized
// ---------------------------------------------------------------------------
__global__ void __launch_bounds__(256)
cvt_hilo(const float* __restrict__ s, __nv_bfloat16* __restrict__ hi,
         __nv_bfloat16* __restrict__ lo)
{
    size_t i = ((size_t)blockIdx.x * 256 + threadIdx.x) * 4;
    float4 v = *(const float4*)(s + i);
    __nv_bfloat16 h0 = __float2bfloat16(v.x);
    __nv_bfloat16 h1 = __float2bfloat16(v.y);
    __nv_bfloat16 h2 = __float2bfloat16(v.z);
    __nv_bfloat16 h3 = __float2bfloat16(v.w);
    __nv_bfloat162* hp = (__nv_bfloat162*)(hi + i);
    hp[0] = __nv_bfloat162{h0, h1};
    hp[1] = __nv_bfloat162{h2, h3};
    __nv_bfloat162* lp = (__nv_bfloat162*)(lo + i);
    lp[0] = __nv_bfloat162{__float2bfloat16(v.x - __bfloat162float(h0)),
                           __float2bfloat16(v.y - __bfloat162float(h1))};
    lp[1] = __nv_bfloat162{__float2bfloat16(v.z - __bfloat162float(h2)),
                           __float2bfloat16(v.w - __bfloat162float(h3))};
}

// ---------------------------------------------------------------------------
// Row softmax (2048 cols) fp32 -> bf16 hi/lo probs
// ---------------------------------------------------------------------------
__global__ void __launch_bounds__(256)
softmax_kernel(const float* __restrict__ S, __nv_bfloat16* __restrict__ Ph,
               __nv_bfloat16* __restrict__ Pl)
{
    const size_t base = (size_t)blockIdx.x * NTOK;
    const int tid = threadIdx.x, lane = tid & 31, wid = tid >> 5;

    float v[8];
    float m = -INFINITY;
#pragma unroll
    for (int i = 0; i < 8; i++) {
        v[i] = S[base + tid + i * 256];
        m = fmaxf(m, v[i]);
    }
#pragma unroll
    for (int off = 16; off > 0; off >>= 1)
        m = fmaxf(m, __shfl_xor_sync(0xFFFFFFFFu, m, off));

    __shared__ float redMax[8], redSum[8];
    if (lane == 0) redMax[wid] = m;
    __syncthreads();
    float bm = -INFINITY;
#pragma unroll
    for (int ww = 0; ww < 8; ww++) bm = fmaxf(bm, redMax[ww]);

    float s = 0.f;
#pragma unroll
    for (int i = 0; i < 8; i++) { v[i] = __expf(v[i] - bm); s += v[i]; }
#pragma unroll
    for (int off = 16; off > 0; off >>= 1)
        s += __shfl_xor_sync(0xFFFFFFFFu, s, off);
    if (lane == 0) redSum[wid] = s;
    __syncthreads();
    float tot = 0.f;
#pragma unroll
    for (int ww = 0; ww < 8; ww++) tot += redSum[ww];
    const float inv = 1.f / tot;

#pragma unroll
    for (int i = 0; i < 8; i++) {
        float p = v[i] * inv;
        __nv_bfloat16 h = __float2bfloat16(p);
        Ph[base + tid + i * 256] = h;
        Pl[base + tid + i * 256] = __float2bfloat16(p - __bfloat162float(h));
    }
}

// ---------------------------------------------------------------------------
// Host driver
// ---------------------------------------------------------------------------
extern "C" void kernel_launch(void* const* d_in, const int* in_sizes, int n_in,
                              void* d_out, int out_size)
{
    const float* ent = (const float*)d_in[0];
    const float* Wq = (const float*)d_in[1];  const float* bq = (const float*)d_in[2];
    const float* Wk = (const float*)d_in[3];  const float* bk = (const float*)d_in[4];
    const float* Wv = (const float*)d_in[5];  const float* bv = (const float*)d_in[6];
    const float* W0 = (const float*)d_in[7];  const float* b0 = (const float*)d_in[8];
    const float* W1 = (const float*)d_in[9];  const float* b1 = (const float*)d_in[10];
    float* out = (float*)d_out;

#define SYM(T, v, s) T* v; cudaGetSymbolAddress((void**)&v, s)
    SYM(float, E32, g_E32);
    SYM(__nv_bfloat16, Ehi, g_Ehi);   SYM(__nv_bfloat16, Elo, g_Elo);
    SYM(__nv_bfloat16, Qhi, g_Qhi);   SYM(__nv_bfloat16, Qlo, g_Qlo);
    SYM(__nv_bfloat16, Khi, g_Khi);   SYM(__nv_bfloat16, Klo, g_Klo);
    SYM(__nv_bfloat16, Vthi, g_Vthi); SYM(__nv_bfloat16, Vtlo, g_Vtlo);
    SYM(__nv_bfloat16, Ohi, g_Ohi);   SYM(__nv_bfloat16, Olo, g_Olo);
    SYM(__nv_bfloat16, Thi, g_Thi);   SYM(__nv_bfloat16, Tlo, g_Tlo);
    SYM(__nv_bfloat16, Wqhi, g_Wqhi); SYM(__nv_bfloat16, Wqlo, g_Wqlo);
    SYM(__nv_bfloat16, Wkhi, g_Wkhi); SYM(__nv_bfloat16, Wklo, g_Wklo);
    SYM(__nv_bfloat16, Wvhi, g_Wvhi); SYM(__nv_bfloat16, Wvlo, g_Wvlo);
    SYM(__nv_bfloat16, W0hi, g_W0hi); SYM(__nv_bfloat16, W0lo, g_W0lo);
    SYM(__nv_bfloat16, W1hi, g_W1hi); SYM(__nv_bfloat16, W1lo, g_W1lo);
    SYM(float, Sb, g_S);
    SYM(__nv_bfloat16, Phi, g_Phi);   SYM(__nv_bfloat16, Plo, g_Plo);
#undef SYM

    cudaFuncSetAttribute(gemm_mma, cudaFuncAttributeMaxDynamicSharedMemorySize, SMEM_TOT);

    const dim3 thrG(512), thr(256);
    const dim3 gFull(16, 8, 1);
    const dim3 gQK(16, 8, NHEADS);
    const dim3 gPV(1, 8, NHEADS);
    const int cvtGrid = (int)(NELEM / 4 / 256);
    const float scale = 0.08838834764831845f;   // 1/sqrt(128)

    cvt_hilo<<<cvtGrid, thr>>>(ent, Ehi, Elo);
    cvt_hilo<<<cvtGrid, thr>>>(Wq, Wqhi, Wqlo);
    cvt_hilo<<<cvtGrid, thr>>>(Wk, Wkhi, Wklo);
    cvt_hilo<<<cvtGrid, thr>>>(Wv, Wvhi, Wvlo);
    cvt_hilo<<<cvtGrid, thr>>>(W0, W0hi, W0lo);
    cvt_hilo<<<cvtGrid, thr>>>(W1, W1hi, W1lo);

    for (int r = 0; r < 2; r++) {
        const float* src32 = (r == 0) ? ent : E32;

        // Q = E @ Wq^T + bq
        gemm_mma<<<gFull, thrG, SMEM_TOT>>>(
            Ehi, Elo, 0, Wqhi, Wqlo, 0, bq, 1, 0, nullptr, 0,
            nullptr, 0, Qhi, Qlo, 0, DMODEL, 1.f);
        // K = E @ Wk^T + bk
        gemm_mma<<<gFull, thrG, SMEM_TOT>>>(
            Ehi, Elo, 0, Wkhi, Wklo, 0, bk, 1, 0, nullptr, 0,
            nullptr, 0, Khi, Klo, 0, DMODEL, 1.f);
        // V^T = Wv @ E^T + bv (row bias)
        gemm_mma<<<gFull, thrG, SMEM_TOT>>>(
            Wvhi, Wvlo, 0, Ehi, Elo, 0, bv, 2, 0, nullptr, 0,
            nullptr, 0, Vthi, Vtlo, 0, DMODEL, 1.f);

        // scores[h] = scale * Q_h @ K_h^T
        gemm_mma<<<gQK, thrG, SMEM_TOT>>>(
            Qhi, Qlo, HDIM, Khi, Klo, HDIM, nullptr, 0, 0, nullptr, 0,
            Sb, SHEAD, nullptr, nullptr, 0, HDIM, scale);

        softmax_kernel<<<NHEADS * NTOK, thr>>>(Sb, Phi, Plo);

        // O[:, h*128:(h+1)*128] = P_h @ Vt_h^T
        gemm_mma<<<gPV, thrG, SMEM_TOT>>>(
            Phi, Plo, SHEAD, Vthi, Vtlo, (unsigned long long)HDIM * DMODEL,
            nullptr, 0, 0, nullptr, 0,
            nullptr, 0, Ohi, Olo, HDIM, NTOK, 1.f);

        // T = relu(O @ W0^T + b0)
        gemm_mma<<<gFull, thrG, SMEM_TOT>>>(
            Ohi, Olo, 0, W0hi, W0lo, 0, b0, 1, 1, nullptr, 0,
            nullptr, 0, Thi, Tlo, 0, DMODEL, 1.f);

        // dst = src + relu(T @ W1^T + b1); round 0 also refreshes E hi/lo
        float* dst = (r == 0) ? E32 : out;
        __nv_bfloat16* nh = (r == 0) ? Ehi : nullptr;
        __nv_bfloat16* nl = (r == 0) ? Elo : nullptr;
        gemm_mma<<<gFull, thrG, SMEM_TOT>>>(
            Thi, Tlo, 0, W1hi, W1lo, 0, b1, 1, 1, src32, 0,
            dst, 0, nh, nl, 0, DMODEL, 1.f);
    }
}